// round 13
// baseline (speedup 1.0000x reference)
#include <cuda_runtime.h>
#include <math.h>

#define BB   96
#define NAA  48
#define FF   128
#define KK   64
#define LL   6
#define NN   (BB*NAA)          // 4608 nodes
#define F3   (3*FF)            // 384
#define CUTR 5.0f
#define WIN  8                 // RBF window (2-aligned start, covers >= ±3 centers)

#define NB_PHI 16
#define NB_MSG 8
#define NB_UPD 8

// upd dynamic smem layout (floats)
#define US_SV   0
#define US_SIN  (US_SV  + NB_UPD*3*FF)
#define US_UV   (US_SIN + NB_UPD*FF)
#define US_VV   (US_UV  + NB_UPD*3*FF)
#define US_VN   (US_VV  + NB_UPD*3*FF)
#define US_HP   (US_VN  + NB_UPD*FF)
#define US_HSH  (US_HP  + 3*NB_UPD*FF)
#define US_ASH  (US_HSH + FF*NB_UPD)
#define US_SVT  (US_ASH + NB_UPD*F3)
#define US_CAT  (US_SVT + F3*NB_UPD)
#define US_TOT  (US_CAT + 2*FF*NB_UPD)     // 23552 floats = 94208 B

// ---------------- device scratch ----------------
__device__ float g_s   [NN*FF];
__device__ float g_v   [NN*F3];
__device__ float g_s2  [NN*FF];
__device__ float g_v2  [NN*F3];
__device__ float g_v2b [NN*F3];
__device__ float g_phi [NN*F3];
__device__ __align__(16) float g_rbfw[NN*NAA*WIN];  // env-premult rbf window
__device__ __align__(16) int4  g_meta[NN*NAA];      // {nbr*F3, (kw>>1)*FF, env_bits, 0}
__device__ float g_dirc[NN*NAA*3];
__device__ int   g_cnt [NN];
__device__ float g_atom[NN];

// ---------------- helpers ----------------
typedef unsigned long long ull;
__device__ __forceinline__ float silu_f(float x) { return x / (1.0f + expf(-x)); }
__device__ __forceinline__ ull pk2(float lo, float hi) {
    ull r; asm("mov.b64 %0, {%1, %2};" : "=l"(r) : "f"(lo), "f"(hi)); return r;
}
__device__ __forceinline__ ull ffma2(ull a, ull b, ull c) {
    ull d; asm("fma.rn.f32x2 %0, %1, %2, %3;" : "=l"(d) : "l"(a), "l"(b), "l"(c)); return d;
}
__device__ __forceinline__ ull add2(ull a, ull b) {
    ull d; asm("add.rn.f32x2 %0, %1, %2;" : "=l"(d) : "l"(a), "l"(b)); return d;
}
__device__ __forceinline__ void upk2(ull a, float& lo, float& hi) {
    asm("mov.b64 {%0, %1}, %2;" : "=f"(lo), "=f"(hi) : "l"(a));
}
__device__ __forceinline__ unsigned smem_u32(const void* p) {
    return (unsigned)__cvta_generic_to_shared(p);
}
#define CP_A16(dst, src) asm volatile("cp.async.cg.shared.global [%0], [%1], 16;" :: "r"(dst), "l"(src))
#define CP_A4(dst, src)  asm volatile("cp.async.ca.shared.global [%0], [%1], 4;"  :: "r"(dst), "l"(src))
#define CP_COMMIT()      asm volatile("cp.async.commit_group;")
#define CP_WAIT0()       asm volatile("cp.async.wait_group 0;")

// ---------------- geometry precompute + neighbor compaction ----------------
__global__ void geom_kernel(const float* __restrict__ pos) {
    const int bi = blockIdx.x;
    const int b  = bi / NAA;
    const int i  = bi % NAA;
    const int t  = threadIdx.x;                // 64

    __shared__ float sd[NAA];
    __shared__ float sdir[NAA][3];
    __shared__ int   smask[NAA];
    __shared__ int   slots[NAA];
    __shared__ int   s_cnt;

    const float* pi = pos + (size_t)(b*NAA + i)*3;
    const float pix = pi[0], piy = pi[1], piz = pi[2];

    if (t < NAA) {
        const float* pj = pos + (size_t)(b*NAA + t)*3;
        float dx = pix - pj[0], dy = piy - pj[1], dz = piz - pj[2];
        float d2 = dx*dx + dy*dy + dz*dz;
        float d  = (t == i) ? 1.0f : sqrtf(d2);
        smask[t] = (t != i) && (d < CUTR);
        sd[t] = d;
        float inv = 1.0f / d;
        sdir[t][0] = dx*inv; sdir[t][1] = dy*inv; sdir[t][2] = dz*inv;
    }
    __syncthreads();
    if (t == 0) {
        int c = 0;
        for (int j = 0; j < NAA; j++) if (smask[j]) slots[c++] = j;
        s_cnt = c;
        g_cnt[bi] = c;
    }
    __syncthreads();
    const int cnt = s_cnt;

    const float GAMMA = (float)(1.0 / ((5.0/64.0)*(5.0/64.0) + 1e-9));
    const float STEP  = (float)(5.0 / 63.0);
    const float PI_F  = 3.14159265358979323846f;

    for (int s = 0; s < cnt; s++) {
        int j = slots[s];
        float d = sd[j];
        float env = 0.5f * (cosf(PI_F * d / CUTR) + 1.0f);
        int ic = __float2int_rn(d / STEP);
        int kw = (ic - 3) & ~1;                // 2-aligned start, coverage >= ±3 centers
        if (kw < 0) kw = 0;
        if (kw > KK - WIN) kw = KK - WIN;      // 56, even
        if (t < WIN) {
            float center = STEP * (float)(kw + t);
            float diff = d - center;
            g_rbfw[((size_t)bi*NAA + s)*WIN + t] = env * expf(-GAMMA * diff * diff);
        } else if (t == WIN) {
            g_meta[(size_t)bi*NAA + s] =
                make_int4((b*NAA + j)*F3, (kw >> 1)*FF, __float_as_int(env), 0);
            g_dirc[((size_t)bi*NAA + s)*3 + 0] = sdir[j][0];
            g_dirc[((size_t)bi*NAA + s)*3 + 1] = sdir[j][1];
            g_dirc[((size_t)bi*NAA + s)*3 + 2] = sdir[j][2];
        }
    }
}

// ---------------- init ----------------
__global__ void init_kernel(const float* __restrict__ emb,
                            const int*   __restrict__ node_atom) {
    const int bi = blockIdx.x;
    const int t  = threadIdx.x;                // 128
    const int a  = node_atom[bi];
    g_s[(size_t)bi*FF + t] = emb[(size_t)a*FF + t];
    g_v[(size_t)bi*F3 + t]          = 0.0f;
    g_v[(size_t)bi*F3 + FF + t]     = 0.0f;
    g_v[(size_t)bi*F3 + 2*FF + t]   = 0.0f;
}

// ---------------- phi (batched, f32x2 node-pairs) ----------------
__global__ __launch_bounds__(384)
void phi_kernel_b(const float* __restrict__ w1, const float* __restrict__ b1,
                  const float* __restrict__ w2, const float* __restrict__ b2) {
    __shared__ __align__(16) float ss[FF][NB_PHI];
    __shared__ __align__(16) float sh[FF][NB_PHI];
    const int t = threadIdx.x;             // 384
    const int node0 = blockIdx.x * NB_PHI;

    for (int idx = t; idx < NB_PHI*FF; idx += 384) {
        int n = idx >> 7, k = idx & 127;
        ss[k][n] = g_s[(size_t)(node0+n)*FF + k];
    }
    __syncthreads();

    if (t < FF) {
        ull acc2[NB_PHI/2];
        float bb = __ldg(&b1[t]);
        ull bb2 = pk2(bb, bb);
        #pragma unroll
        for (int i = 0; i < NB_PHI/2; i++) acc2[i] = bb2;
        #pragma unroll 4
        for (int k = 0; k < FF; k++) {
            float w = __ldg(&w1[k*FF + t]);
            ull w2p = pk2(w, w);
            const ulonglong2* sp = (const ulonglong2*)&ss[k][0];
            ulonglong2 q0 = sp[0], q1 = sp[1], q2 = sp[2], q3 = sp[3];
            acc2[0] = ffma2(q0.x, w2p, acc2[0]);
            acc2[1] = ffma2(q0.y, w2p, acc2[1]);
            acc2[2] = ffma2(q1.x, w2p, acc2[2]);
            acc2[3] = ffma2(q1.y, w2p, acc2[3]);
            acc2[4] = ffma2(q2.x, w2p, acc2[4]);
            acc2[5] = ffma2(q2.y, w2p, acc2[5]);
            acc2[6] = ffma2(q3.x, w2p, acc2[6]);
            acc2[7] = ffma2(q3.y, w2p, acc2[7]);
        }
        #pragma unroll
        for (int i = 0; i < NB_PHI/2; i++) {
            float lo, hi; upk2(acc2[i], lo, hi);
            sh[t][2*i]   = silu_f(lo);
            sh[t][2*i+1] = silu_f(hi);
        }
    }
    __syncthreads();

    {
        ull acc2[NB_PHI/2];
        float bb = __ldg(&b2[t]);
        ull bb2 = pk2(bb, bb);
        #pragma unroll
        for (int i = 0; i < NB_PHI/2; i++) acc2[i] = bb2;
        #pragma unroll 4
        for (int k = 0; k < FF; k++) {
            float w = __ldg(&w2[k*F3 + t]);
            ull w2p = pk2(w, w);
            const ulonglong2* sp = (const ulonglong2*)&sh[k][0];
            ulonglong2 q0 = sp[0], q1 = sp[1], q2 = sp[2], q3 = sp[3];
            acc2[0] = ffma2(q0.x, w2p, acc2[0]);
            acc2[1] = ffma2(q0.y, w2p, acc2[1]);
            acc2[2] = ffma2(q1.x, w2p, acc2[2]);
            acc2[3] = ffma2(q1.y, w2p, acc2[3]);
            acc2[4] = ffma2(q2.x, w2p, acc2[4]);
            acc2[5] = ffma2(q2.y, w2p, acc2[5]);
            acc2[6] = ffma2(q3.x, w2p, acc2[6]);
            acc2[7] = ffma2(q3.y, w2p, acc2[7]);
        }
        #pragma unroll
        for (int i = 0; i < NB_PHI/2; i++) {
            float lo, hi; upk2(acc2[i], lo, hi);
            g_phi[(size_t)(node0+2*i)*F3   + t] = lo;
            g_phi[(size_t)(node0+2*i+1)*F3 + t] = hi;
        }
    }
}

// ---------------- message block: WIN=8 + int4 meta + cp.async + prefetch ----------
__global__ __launch_bounds__(128, 5)
void msg_kernel_w(const float* __restrict__ rbf_w, const float* __restrict__ rbf_b) {
    __shared__ __align__(16) ull   s_wp[(KK/2)*FF];     // 32 KB packed W pairs [p][f]
    __shared__ __align__(16) float s_rbfw[2][NAA*WIN];  // 3 KB double-buffered
    __shared__ __align__(16) int4  s_meta[2][NAA];      // 1.5 KB
    __shared__ float s_dir[2][NAA*3];

    const int f = threadIdx.x;                 // 128
    const int chunk = blockIdx.y;              // 0..2
    const int t = chunk*FF + f;
    const int node0 = blockIdx.x * NB_MSG;

    // stage this chunk's W slice as f32x2 pairs: s_wp[p*FF+f] = (w[2p][t], w[2p+1][t])
    for (int idx = f; idx < (KK/2)*FF; idx += 128) {
        int p = idx >> 7, ff = idx & 127;
        s_wp[idx] = pk2(__ldg(&rbf_w[(2*p)*F3   + chunk*FF + ff]),
                        __ldg(&rbf_w[(2*p+1)*F3 + chunk*FF + ff]));
    }
    const float bias = __ldg(&rbf_b[t]);

    // async-stage node 0 into buffer 0
    {
        const int bi = node0;
        const int c0 = g_cnt[bi];
        const float4* src4 = (const float4*)(g_rbfw + (size_t)bi*NAA*WIN);
        for (int idx = f; idx < c0*2; idx += 128)
            CP_A16(smem_u32(&s_rbfw[0][0]) + idx*16, src4 + idx);
        if (chunk == 2)
            for (int idx = f; idx < c0*3; idx += 128)
                CP_A4(smem_u32(&s_dir[0][0]) + idx*4, g_dirc + (size_t)bi*NAA*3 + idx);
        if (f < c0)
            CP_A16(smem_u32(&s_meta[0][0]) + f*16, g_meta + (size_t)bi*NAA + f);
        CP_COMMIT();
    }
    CP_WAIT0();
    __syncthreads();

    const float* phiT = g_phi + t;
    const float* vT   = g_v + f;
    const ull*   wpF  = s_wp + f;

    for (int n = 0; n < NB_MSG; n++) {
        const int bi = node0 + n;
        const int cnt = g_cnt[bi];
        const int buf = n & 1;

        // issue async staging for node n+1 into the other buffer
        if (n + 1 < NB_MSG) {
            const int bj = bi + 1;
            const int c1 = g_cnt[bj];
            const int ob = buf ^ 1;
            const float4* src4 = (const float4*)(g_rbfw + (size_t)bj*NAA*WIN);
            for (int idx = f; idx < c1*2; idx += 128)
                CP_A16(smem_u32(&s_rbfw[ob][0]) + idx*16, src4 + idx);
            if (chunk == 2)
                for (int idx = f; idx < c1*3; idx += 128)
                    CP_A4(smem_u32(&s_dir[ob][0]) + idx*4, g_dirc + (size_t)bj*NAA*3 + idx);
            if (f < c1)
                CP_A16(smem_u32(&s_meta[ob][0]) + f*16, g_meta + (size_t)bj*NAA + f);
            CP_COMMIT();
        }

        float ac0 = 0.0f, ac1 = 0.0f, ac2 = 0.0f;

        // ---- software-pipelined edge loop ----
        float pA = 0.f, pB = 0.f;
        float vA0 = 0.f, vA1 = 0.f, vA2 = 0.f, vB0 = 0.f, vB1 = 0.f, vB2 = 0.f;
        if (cnt > 0) {
            int o0 = s_meta[buf][0].x;
            pA = __ldg(phiT + o0);
            if (chunk == 1) {
                vA0 = __ldg(vT + o0); vA1 = __ldg(vT + o0 + FF); vA2 = __ldg(vT + o0 + 2*FF);
            }
        }
        if (cnt > 1) {
            int o1 = s_meta[buf][1].x;
            pB = __ldg(phiT + o1);
            if (chunk == 1) {
                vB0 = __ldg(vT + o1); vB1 = __ldg(vT + o1 + FF); vB2 = __ldg(vT + o1 + 2*FF);
            }
        }

        int s = 0;
        for (; s + 2 <= cnt; s += 2) {
            int4 mA = s_meta[buf][s];
            int4 mB = s_meta[buf][s+1];

            // prefetch next pair
            float pC, pD, vC0=0.f, vC1=0.f, vC2=0.f, vD0=0.f, vD1=0.f, vD2=0.f;
            {
                int i2 = s + 2 < cnt ? s + 2 : cnt - 1;
                int i3 = s + 3 < cnt ? s + 3 : cnt - 1;
                int o2 = s_meta[buf][i2].x, o3 = s_meta[buf][i3].x;
                pC = __ldg(phiT + o2);
                pD = __ldg(phiT + o3);
                if (chunk == 1) {
                    vC0 = __ldg(vT + o2); vC1 = __ldg(vT + o2 + FF); vC2 = __ldg(vT + o2 + 2*FF);
                    vD0 = __ldg(vT + o3); vD1 = __ldg(vT + o3 + FF); vD2 = __ldg(vT + o3 + 2*FF);
                }
            }

            // dots for edges s, s+1
            const ulonglong2* rwA = (const ulonglong2*)(&s_rbfw[buf][0] + s*WIN);
            const ulonglong2* rwB = (const ulonglong2*)(&s_rbfw[buf][0] + (s+1)*WIN);
            ulonglong2 aP = rwA[0], aQ = rwA[1];
            ulonglong2 bP = rwB[0], bQ = rwB[1];
            const ull* pwA = wpF + mA.y;
            const ull* pwB = wpF + mB.y;
            ull x0 = ffma2(aP.x, pwA[0*FF], 0ull);
            ull x1 = ffma2(aP.y, pwA[1*FF], 0ull);
            ull y0 = ffma2(bP.x, pwB[0*FF], 0ull);
            ull y1 = ffma2(bP.y, pwB[1*FF], 0ull);
            x0 = ffma2(aQ.x, pwA[2*FF], x0);
            x1 = ffma2(aQ.y, pwA[3*FF], x1);
            y0 = ffma2(bQ.x, pwB[2*FF], y0);
            y1 = ffma2(bQ.y, pwB[3*FF], y1);
            ull sa = add2(x0, x1), sb = add2(y0, y1);
            float la, ha, lb, hb;
            upk2(sa, la, ha); upk2(sb, lb, hb);
            float tvalA = fmaf(__int_as_float(mA.z), bias, la + ha);
            float tvalB = fmaf(__int_as_float(mB.z), bias, lb + hb);

            float xA = pA * tvalA;
            float xB = pB * tvalB;

            if (chunk == 0) {
                ac0 += xA + xB;
            } else if (chunk == 1) {
                ac0 = fmaf(xA, vA0, ac0); ac1 = fmaf(xA, vA1, ac1); ac2 = fmaf(xA, vA2, ac2);
                ac0 = fmaf(xB, vB0, ac0); ac1 = fmaf(xB, vB1, ac1); ac2 = fmaf(xB, vB2, ac2);
            } else {
                ac0 = fmaf(xA, s_dir[buf][s*3+0], ac0);
                ac1 = fmaf(xA, s_dir[buf][s*3+1], ac1);
                ac2 = fmaf(xA, s_dir[buf][s*3+2], ac2);
                ac0 = fmaf(xB, s_dir[buf][s*3+3], ac0);
                ac1 = fmaf(xB, s_dir[buf][s*3+4], ac1);
                ac2 = fmaf(xB, s_dir[buf][s*3+5], ac2);
            }

            pA = pC; pB = pD;
            vA0 = vC0; vA1 = vC1; vA2 = vC2;
            vB0 = vD0; vB1 = vD1; vB2 = vD2;
        }
        if (s < cnt) {          // odd tail
            int4 mA = s_meta[buf][s];
            const ulonglong2* rw = (const ulonglong2*)(&s_rbfw[buf][0] + s*WIN);
            ulonglong2 aP = rw[0], aQ = rw[1];
            const ull* pw = wpF + mA.y;
            ull x0 = ffma2(aP.x, pw[0*FF], 0ull);
            ull x1 = ffma2(aP.y, pw[1*FF], 0ull);
            x0 = ffma2(aQ.x, pw[2*FF], x0);
            x1 = ffma2(aQ.y, pw[3*FF], x1);
            ull sa = add2(x0, x1);
            float lo, hi; upk2(sa, lo, hi);
            float tval = fmaf(__int_as_float(mA.z), bias, lo + hi);
            float xA = pA * tval;
            if (chunk == 0) {
                ac0 += xA;
            } else if (chunk == 1) {
                ac0 = fmaf(xA, vA0, ac0); ac1 = fmaf(xA, vA1, ac1); ac2 = fmaf(xA, vA2, ac2);
            } else {
                ac0 = fmaf(xA, s_dir[buf][s*3+0], ac0);
                ac1 = fmaf(xA, s_dir[buf][s*3+1], ac1);
                ac2 = fmaf(xA, s_dir[buf][s*3+2], ac2);
            }
        }

        // writeback
        if (chunk == 0) {
            g_s2[(size_t)bi*FF + f] = __ldg(&g_s[(size_t)bi*FF + f]) + ac0;
        } else if (chunk == 1) {
            size_t base = (size_t)bi*F3;
            g_v2[base + f]        = __ldg(&g_v[base + f])        + ac0;
            g_v2[base + FF + f]   = __ldg(&g_v[base + FF + f])   + ac1;
            g_v2[base + 2*FF + f] = __ldg(&g_v[base + 2*FF + f]) + ac2;
        } else {
            size_t base = (size_t)bi*F3;
            g_v2b[base + f]        = ac0;
            g_v2b[base + FF + f]   = ac1;
            g_v2b[base + 2*FF + f] = ac2;
        }

        CP_WAIT0();
        __syncthreads();
    }
}

// ---------------- update block (batched x8, f32x2 node-pairs) ----------------
__global__ __launch_bounds__(384, 2)
void upd_kernel_b(const float* __restrict__ U,  const float* __restrict__ V,
                  const float* __restrict__ w1, const float* __restrict__ b1,
                  const float* __restrict__ w2, const float* __restrict__ b2) {
    extern __shared__ float usm[];
    float* sv   = usm + US_SV;
    float* s_in = usm + US_SIN;
    float* Uvs  = usm + US_UV;
    float* Vvs  = usm + US_VV;
    float* Vn   = usm + US_VN;
    float* hp   = usm + US_HP;
    float* hsh  = usm + US_HSH;
    float* ash  = usm + US_ASH;
    float* sv_t = usm + US_SVT;
    float* cat_t= usm + US_CAT;

    const int t = threadIdx.x;             // 384
    const int node0 = blockIdx.x * NB_UPD;
    const int g = t & 127;
    const int m = t >> 7;                  // 0..2

    for (int idx = t; idx < NB_UPD*F3; idx += 384) {
        float val = g_v2[(size_t)node0*F3 + idx] + g_v2b[(size_t)node0*F3 + idx];
        sv[idx] = val;
        int n = idx / F3, r = idx - n*F3;
        sv_t[r*NB_UPD + n] = val;
    }
    for (int idx = t; idx < NB_UPD*FF; idx += 384)
        s_in[idx] = g_s2[(size_t)node0*FF + idx];
    __syncthreads();

    // Phase A: Uv, Vv  (packed node-pairs)
    {
        ull aU2[NB_UPD/2] = {0,0,0,0}, aV2[NB_UPD/2] = {0,0,0,0};
        #pragma unroll 4
        for (int k = 0; k < FF; k++) {
            float u  = __ldg(&U[k*FF + g]);
            float vw = __ldg(&V[k*FF + g]);
            ull u2  = pk2(u, u);
            ull vw2 = pk2(vw, vw);
            const ulonglong2* sp = (const ulonglong2*)(sv_t + (m*FF + k)*NB_UPD);
            ulonglong2 q0 = sp[0], q1 = sp[1];
            aU2[0] = ffma2(q0.x, u2,  aU2[0]);
            aU2[1] = ffma2(q0.y, u2,  aU2[1]);
            aU2[2] = ffma2(q1.x, u2,  aU2[2]);
            aU2[3] = ffma2(q1.y, u2,  aU2[3]);
            aV2[0] = ffma2(q0.x, vw2, aV2[0]);
            aV2[1] = ffma2(q0.y, vw2, aV2[1]);
            aV2[2] = ffma2(q1.x, vw2, aV2[2]);
            aV2[3] = ffma2(q1.y, vw2, aV2[3]);
        }
        #pragma unroll
        for (int i = 0; i < NB_UPD/2; i++) {
            float lo, hi;
            upk2(aU2[i], lo, hi);
            Uvs[((2*i)*3 + m)*FF + g]   = lo;
            Uvs[((2*i+1)*3 + m)*FF + g] = hi;
            upk2(aV2[i], lo, hi);
            Vvs[((2*i)*3 + m)*FF + g]   = lo;
            Vvs[((2*i+1)*3 + m)*FF + g] = hi;
        }
    }
    __syncthreads();

    for (int idx = t; idx < NB_UPD*FF; idx += 384) {
        int n = idx >> 7, gg = idx & 127;
        float v0 = Vvs[(n*3+0)*FF+gg], v1 = Vvs[(n*3+1)*FF+gg], v2 = Vvs[(n*3+2)*FF+gg];
        Vn[n*FF + gg] = sqrtf(v0*v0 + v1*v1 + v2*v2 + 1e-8f);
    }
    __syncthreads();

    for (int idx = t; idx < NB_UPD*2*FF; idx += 384) {
        int n = idx >> 8, k = idx & 255;
        float c = (k < FF) ? s_in[n*FF + k] : Vn[n*FF + (k-FF)];
        cat_t[k*NB_UPD + n] = c;
    }
    __syncthreads();

    // Phase B: h partial (k-split across m-groups), packed node-pairs
    {
        int k0 = m*86, k1 = (m == 2) ? 256 : (k0 + 86);
        ull acc2[NB_UPD/2] = {0,0,0,0};
        #pragma unroll 2
        for (int k = k0; k < k1; k++) {
            float w = __ldg(&w1[k*FF + g]);
            ull w2p = pk2(w, w);
            const ulonglong2* sp = (const ulonglong2*)(cat_t + k*NB_UPD);
            ulonglong2 q0 = sp[0], q1 = sp[1];
            acc2[0] = ffma2(q0.x, w2p, acc2[0]);
            acc2[1] = ffma2(q0.y, w2p, acc2[1]);
            acc2[2] = ffma2(q1.x, w2p, acc2[2]);
            acc2[3] = ffma2(q1.y, w2p, acc2[3]);
        }
        #pragma unroll
        for (int i = 0; i < NB_UPD/2; i++) {
            float lo, hi; upk2(acc2[i], lo, hi);
            hp[(m*NB_UPD + 2*i)*FF + g]   = lo;
            hp[(m*NB_UPD + 2*i+1)*FF + g] = hi;
        }
    }
    __syncthreads();

    for (int idx = t; idx < NB_UPD*FF; idx += 384) {
        int n = idx >> 7, gg = idx & 127;
        float hs = hp[(0*NB_UPD+n)*FF+gg] + hp[(1*NB_UPD+n)*FF+gg] + hp[(2*NB_UPD+n)*FF+gg]
                 + __ldg(&b1[gg]);
        hsh[gg*NB_UPD + n] = silu_f(hs);
    }
    __syncthreads();

    // Phase C: a = h @ w2 + b2, packed node-pairs
    {
        ull acc2[NB_UPD/2];
        float bb = __ldg(&b2[t]);
        ull bb2 = pk2(bb, bb);
        #pragma unroll
        for (int i = 0; i < NB_UPD/2; i++) acc2[i] = bb2;
        #pragma unroll 4
        for (int k = 0; k < FF; k++) {
            float w = __ldg(&w2[k*F3 + t]);
            ull w2p = pk2(w, w);
            const ulonglong2* sp = (const ulonglong2*)(hsh + k*NB_UPD);
            ulonglong2 q0 = sp[0], q1 = sp[1];
            acc2[0] = ffma2(q0.x, w2p, acc2[0]);
            acc2[1] = ffma2(q0.y, w2p, acc2[1]);
            acc2[2] = ffma2(q1.x, w2p, acc2[2]);
            acc2[3] = ffma2(q1.y, w2p, acc2[3]);
        }
        #pragma unroll
        for (int i = 0; i < NB_UPD/2; i++) {
            float lo, hi; upk2(acc2[i], lo, hi);
            ash[(2*i)*F3 + t]   = lo;
            ash[(2*i+1)*F3 + t] = hi;
        }
    }
    __syncthreads();

    for (int idx = t; idx < NB_UPD*FF; idx += 384) {
        int n = idx >> 7, gg = idx & 127;
        float avv = ash[n*F3 + gg], asv = ash[n*F3 + FF+gg], ass = ash[n*F3 + 2*FF+gg];
        float u0 = Uvs[(n*3+0)*FF+gg], u1 = Uvs[(n*3+1)*FF+gg], u2 = Uvs[(n*3+2)*FF+gg];
        float w0 = Vvs[(n*3+0)*FF+gg], w1v = Vvs[(n*3+1)*FF+gg], w2v = Vvs[(n*3+2)*FF+gg];
        float dot = u0*w0 + u1*w1v + u2*w2v;
        size_t vb = (size_t)(node0+n)*F3;
        g_v[vb + gg]        = sv[(n*3+0)*FF+gg] + avv*u0;
        g_v[vb + FF + gg]   = sv[(n*3+1)*FF+gg] + avv*u1;
        g_v[vb + 2*FF + gg] = sv[(n*3+2)*FF+gg] + avv*u2;
        g_s[(size_t)(node0+n)*FF + gg] = s_in[n*FF + gg] + asv*dot + ass;
    }
}

// ---------------- output head ----------------
__global__ void out_atom_kernel(const float* __restrict__ w1, const float* __restrict__ b1,
                                const float* __restrict__ w2, const float* __restrict__ b2) {
    const int bi = blockIdx.x;
    const int t  = threadIdx.x;                // 128
    __shared__ float ss[FF];
    __shared__ float red[FF];
    ss[t] = g_s[(size_t)bi*FF + t];
    __syncthreads();
    float acc = __ldg(&b1[t]);
    #pragma unroll 8
    for (int k = 0; k < FF; k++) acc = fmaf(ss[k], __ldg(&w1[k*FF + t]), acc);
    float h = silu_f(acc);
    red[t] = h * __ldg(&w2[t]);
    __syncthreads();
    for (int ofs = 64; ofs > 0; ofs >>= 1) {
        if (t < ofs) red[t] += red[t + ofs];
        __syncthreads();
    }
    if (t == 0) g_atom[bi] = red[0] + __ldg(&b2[0]);
}

__global__ void out_reduce_kernel(float* __restrict__ out) {
    const int b = blockIdx.x;
    const int t = threadIdx.x;                 // 64
    __shared__ float r[64];
    r[t] = (t < NAA) ? g_atom[(size_t)b*NAA + t] : 0.0f;
    __syncthreads();
    for (int ofs = 32; ofs > 0; ofs >>= 1) {
        if (t < ofs) r[t] += r[t + ofs];
        __syncthreads();
    }
    if (t == 0) out[b] = r[0];
}

// ---------------- launch ----------------
extern "C" void kernel_launch(void* const* d_in, const int* in_sizes, int n_in,
                              void* d_out, int out_size) {
    const float* pos       = (const float*)d_in[1];
    const int*   node_atom = (const int*)  d_in[3];
    const float* emb       = (const float*)d_in[4];
    const float* msg_w1    = (const float*)d_in[5];
    const float* msg_b1    = (const float*)d_in[6];
    const float* msg_w2    = (const float*)d_in[7];
    const float* msg_b2    = (const float*)d_in[8];
    const float* rbf_w     = (const float*)d_in[9];
    const float* rbf_b     = (const float*)d_in[10];
    const float* upd_U     = (const float*)d_in[11];
    const float* upd_V     = (const float*)d_in[12];
    const float* upd_w1    = (const float*)d_in[13];
    const float* upd_b1    = (const float*)d_in[14];
    const float* upd_w2    = (const float*)d_in[15];
    const float* upd_b2    = (const float*)d_in[16];
    const float* out_w1    = (const float*)d_in[17];
    const float* out_b1    = (const float*)d_in[18];
    const float* out_w2    = (const float*)d_in[19];
    const float* out_b2    = (const float*)d_in[20];

    const int upd_smem = US_TOT * sizeof(float);   // ~94 KB
    cudaFuncSetAttribute(upd_kernel_b, cudaFuncAttributeMaxDynamicSharedMemorySize, upd_smem);

    geom_kernel<<<NN, 64>>>(pos);
    init_kernel<<<NN, FF>>>(emb, node_atom);

    dim3 msg_grid(NN/NB_MSG, 3);
    for (int l = 0; l < LL; l++) {
        phi_kernel_b<<<NN/NB_PHI, 384>>>(msg_w1 + (size_t)l*FF*FF, msg_b1 + (size_t)l*FF,
                                         msg_w2 + (size_t)l*FF*F3, msg_b2 + (size_t)l*F3);
        msg_kernel_w<<<msg_grid, 128>>>(rbf_w + (size_t)l*KK*F3, rbf_b + (size_t)l*F3);
        upd_kernel_b<<<NN/NB_UPD, 384, upd_smem>>>(upd_U + (size_t)l*FF*FF, upd_V + (size_t)l*FF*FF,
                                                   upd_w1 + (size_t)l*2*FF*FF, upd_b1 + (size_t)l*FF,
                                                   upd_w2 + (size_t)l*FF*F3,   upd_b2 + (size_t)l*F3);
    }

    out_atom_kernel<<<NN, FF>>>(out_w1, out_b1, out_w2, out_b2);
    out_reduce_kernel<<<BB, 64>>>((float*)d_out);
}

// round 14
// speedup vs baseline: 1.0280x; 1.0280x over previous
#include <cuda_runtime.h>
#include <math.h>

#define BB   96
#define NAA  48
#define FF   128
#define KK   64
#define LL   6
#define NN   (BB*NAA)          // 4608 nodes
#define F3   (3*FF)            // 384
#define CUTR 5.0f
#define WIN  8                 // RBF window (2-aligned start, covers >= ±3 centers)

#define NB_PHI 16
#define NB_MSG 8
#define NB_UPD 8

// upd dynamic smem layout (floats)
#define US_SV   0
#define US_SIN  (US_SV  + NB_UPD*3*FF)
#define US_UV   (US_SIN + NB_UPD*FF)
#define US_VV   (US_UV  + NB_UPD*3*FF)
#define US_VN   (US_VV  + NB_UPD*3*FF)
#define US_HP   (US_VN  + NB_UPD*FF)
#define US_HSH  (US_HP  + 3*NB_UPD*FF)
#define US_ASH  (US_HSH + FF*NB_UPD)
#define US_SVT  (US_ASH + NB_UPD*F3)
#define US_CAT  (US_SVT + F3*NB_UPD)
#define US_TOT  (US_CAT + 2*FF*NB_UPD)     // 23552 floats = 94208 B

// ---------------- device scratch ----------------
__device__ float g_s   [NN*FF];
__device__ float g_v   [NN*F3];
__device__ float g_s2  [NN*FF];
__device__ float g_v2  [NN*F3];
__device__ float g_v2b [NN*F3];
__device__ float g_phi [NN*F3];
__device__ __align__(16) float g_rbfw[NN*NAA*WIN];  // env-premult rbf window
__device__ __align__(16) int4  g_meta[NN*NAA];      // {nbr*F3, (kw>>1)*FF, env_bits, 0}
__device__ float g_dirc[NN*NAA*3];
__device__ int   g_cnt [NN];
__device__ float g_atom[NN];

// ---------------- helpers ----------------
typedef unsigned long long ull;
__device__ __forceinline__ float silu_f(float x) { return x / (1.0f + expf(-x)); }
__device__ __forceinline__ ull pk2(float lo, float hi) {
    ull r; asm("mov.b64 %0, {%1, %2};" : "=l"(r) : "f"(lo), "f"(hi)); return r;
}
__device__ __forceinline__ ull ffma2(ull a, ull b, ull c) {
    ull d; asm("fma.rn.f32x2 %0, %1, %2, %3;" : "=l"(d) : "l"(a), "l"(b), "l"(c)); return d;
}
__device__ __forceinline__ ull add2(ull a, ull b) {
    ull d; asm("add.rn.f32x2 %0, %1, %2;" : "=l"(d) : "l"(a), "l"(b)); return d;
}
__device__ __forceinline__ void upk2(ull a, float& lo, float& hi) {
    asm("mov.b64 {%0, %1}, %2;" : "=f"(lo), "=f"(hi) : "l"(a));
}
__device__ __forceinline__ unsigned smem_u32(const void* p) {
    return (unsigned)__cvta_generic_to_shared(p);
}
#define CP_A16(dst, src) asm volatile("cp.async.cg.shared.global [%0], [%1], 16;" :: "r"(dst), "l"(src))
#define CP_A4(dst, src)  asm volatile("cp.async.ca.shared.global [%0], [%1], 4;"  :: "r"(dst), "l"(src))
#define CP_COMMIT()      asm volatile("cp.async.commit_group;")
#define CP_WAIT0()       asm volatile("cp.async.wait_group 0;")

// ---------------- geometry precompute + neighbor compaction ----------------
__global__ void geom_kernel(const float* __restrict__ pos) {
    const int bi = blockIdx.x;
    const int b  = bi / NAA;
    const int i  = bi % NAA;
    const int t  = threadIdx.x;                // 64

    __shared__ float sd[NAA];
    __shared__ float sdir[NAA][3];
    __shared__ int   smask[NAA];
    __shared__ int   slots[NAA];
    __shared__ int   s_cnt;

    const float* pi = pos + (size_t)(b*NAA + i)*3;
    const float pix = pi[0], piy = pi[1], piz = pi[2];

    if (t < NAA) {
        const float* pj = pos + (size_t)(b*NAA + t)*3;
        float dx = pix - pj[0], dy = piy - pj[1], dz = piz - pj[2];
        float d2 = dx*dx + dy*dy + dz*dz;
        float d  = (t == i) ? 1.0f : sqrtf(d2);
        smask[t] = (t != i) && (d < CUTR);
        sd[t] = d;
        float inv = 1.0f / d;
        sdir[t][0] = dx*inv; sdir[t][1] = dy*inv; sdir[t][2] = dz*inv;
    }
    __syncthreads();
    if (t == 0) {
        int c = 0;
        for (int j = 0; j < NAA; j++) if (smask[j]) slots[c++] = j;
        s_cnt = c;
        g_cnt[bi] = c;
    }
    __syncthreads();
    const int cnt = s_cnt;

    const float GAMMA = (float)(1.0 / ((5.0/64.0)*(5.0/64.0) + 1e-9));
    const float STEP  = (float)(5.0 / 63.0);
    const float PI_F  = 3.14159265358979323846f;

    for (int s = 0; s < cnt; s++) {
        int j = slots[s];
        float d = sd[j];
        float env = 0.5f * (cosf(PI_F * d / CUTR) + 1.0f);
        int ic = __float2int_rn(d / STEP);
        int kw = (ic - 3) & ~1;                // 2-aligned start, coverage >= ±3 centers
        if (kw < 0) kw = 0;
        if (kw > KK - WIN) kw = KK - WIN;      // 56, even
        if (t < WIN) {
            float center = STEP * (float)(kw + t);
            float diff = d - center;
            g_rbfw[((size_t)bi*NAA + s)*WIN + t] = env * expf(-GAMMA * diff * diff);
        } else if (t == WIN) {
            g_meta[(size_t)bi*NAA + s] =
                make_int4((b*NAA + j)*F3, (kw >> 1)*FF, __float_as_int(env), 0);
            g_dirc[((size_t)bi*NAA + s)*3 + 0] = sdir[j][0];
            g_dirc[((size_t)bi*NAA + s)*3 + 1] = sdir[j][1];
            g_dirc[((size_t)bi*NAA + s)*3 + 2] = sdir[j][2];
        }
    }
}

// ---------------- init ----------------
__global__ void init_kernel(const float* __restrict__ emb,
                            const int*   __restrict__ node_atom) {
    const int bi = blockIdx.x;
    const int t  = threadIdx.x;                // 128
    const int a  = node_atom[bi];
    g_s[(size_t)bi*FF + t] = emb[(size_t)a*FF + t];
    g_v[(size_t)bi*F3 + t]          = 0.0f;
    g_v[(size_t)bi*F3 + FF + t]     = 0.0f;
    g_v[(size_t)bi*F3 + 2*FF + t]   = 0.0f;
}

// ---------------- phi (batched, split-k first GEMM across 3 warp-groups) ---------
__global__ __launch_bounds__(384)
void phi_kernel_b(const float* __restrict__ w1, const float* __restrict__ b1,
                  const float* __restrict__ w2, const float* __restrict__ b2) {
    __shared__ __align__(16) float ss[FF][NB_PHI];
    __shared__ __align__(16) float sh[FF][NB_PHI];
    __shared__ __align__(16) float hp[3][FF][NB_PHI];   // split-k partials
    const int t = threadIdx.x;             // 384
    const int g = t & 127;
    const int m = t >> 7;                  // 0..2
    const int node0 = blockIdx.x * NB_PHI;

    for (int idx = t; idx < NB_PHI*FF; idx += 384) {
        int n = idx >> 7, k = idx & 127;
        ss[k][n] = g_s[(size_t)(node0+n)*FF + k];
    }
    __syncthreads();

    // first GEMM: split k across m-groups
    {
        const int k0 = (m == 0) ? 0 : (m == 1 ? 43 : 86);
        const int k1 = (m == 0) ? 43 : (m == 1 ? 86 : 128);
        ull acc2[NB_PHI/2] = {0,0,0,0,0,0,0,0};
        for (int k = k0; k < k1; k++) {
            float w = __ldg(&w1[k*FF + g]);
            ull w2p = pk2(w, w);
            const ulonglong2* sp = (const ulonglong2*)&ss[k][0];
            ulonglong2 q0 = sp[0], q1 = sp[1], q2 = sp[2], q3 = sp[3];
            acc2[0] = ffma2(q0.x, w2p, acc2[0]);
            acc2[1] = ffma2(q0.y, w2p, acc2[1]);
            acc2[2] = ffma2(q1.x, w2p, acc2[2]);
            acc2[3] = ffma2(q1.y, w2p, acc2[3]);
            acc2[4] = ffma2(q2.x, w2p, acc2[4]);
            acc2[5] = ffma2(q2.y, w2p, acc2[5]);
            acc2[6] = ffma2(q3.x, w2p, acc2[6]);
            acc2[7] = ffma2(q3.y, w2p, acc2[7]);
        }
        #pragma unroll
        for (int i = 0; i < NB_PHI/2; i++) {
            float lo, hi; upk2(acc2[i], lo, hi);
            hp[m][g][2*i]   = lo;
            hp[m][g][2*i+1] = hi;
        }
    }
    __syncthreads();

    for (int idx = t; idx < FF*NB_PHI; idx += 384) {
        int k = idx >> 4, n = idx & 15;
        float hs = hp[0][k][n] + hp[1][k][n] + hp[2][k][n] + __ldg(&b1[k]);
        sh[k][n] = silu_f(hs);
    }
    __syncthreads();

    // second GEMM: all 384 threads, one output column each
    {
        ull acc2[NB_PHI/2];
        float bb = __ldg(&b2[t]);
        ull bb2 = pk2(bb, bb);
        #pragma unroll
        for (int i = 0; i < NB_PHI/2; i++) acc2[i] = bb2;
        for (int k = 0; k < FF; k++) {
            float w = __ldg(&w2[k*F3 + t]);
            ull w2p = pk2(w, w);
            const ulonglong2* sp = (const ulonglong2*)&sh[k][0];
            ulonglong2 q0 = sp[0], q1 = sp[1], q2 = sp[2], q3 = sp[3];
            acc2[0] = ffma2(q0.x, w2p, acc2[0]);
            acc2[1] = ffma2(q0.y, w2p, acc2[1]);
            acc2[2] = ffma2(q1.x, w2p, acc2[2]);
            acc2[3] = ffma2(q1.y, w2p, acc2[3]);
            acc2[4] = ffma2(q2.x, w2p, acc2[4]);
            acc2[5] = ffma2(q2.y, w2p, acc2[5]);
            acc2[6] = ffma2(q3.x, w2p, acc2[6]);
            acc2[7] = ffma2(q3.y, w2p, acc2[7]);
        }
        #pragma unroll
        for (int i = 0; i < NB_PHI/2; i++) {
            float lo, hi; upk2(acc2[i], lo, hi);
            g_phi[(size_t)(node0+2*i)*F3   + t] = lo;
            g_phi[(size_t)(node0+2*i+1)*F3 + t] = hi;
        }
    }
}

// ---------------- message block: WIN=8 + int4 meta + cp.async + prefetch ----------
__global__ __launch_bounds__(128, 5)
void msg_kernel_w(const float* __restrict__ rbf_w, const float* __restrict__ rbf_b) {
    __shared__ __align__(16) ull   s_wp[(KK/2)*FF];     // 32 KB packed W pairs [p][f]
    __shared__ __align__(16) float s_rbfw[2][NAA*WIN];  // 3 KB double-buffered
    __shared__ __align__(16) int4  s_meta[2][NAA];      // 1.5 KB
    __shared__ float s_dir[2][NAA*3];

    const int f = threadIdx.x;                 // 128
    const int chunk = blockIdx.y;              // 0..2
    const int t = chunk*FF + f;
    const int node0 = blockIdx.x * NB_MSG;

    for (int idx = f; idx < (KK/2)*FF; idx += 128) {
        int p = idx >> 7, ff = idx & 127;
        s_wp[idx] = pk2(__ldg(&rbf_w[(2*p)*F3   + chunk*FF + ff]),
                        __ldg(&rbf_w[(2*p+1)*F3 + chunk*FF + ff]));
    }
    const float bias = __ldg(&rbf_b[t]);

    // async-stage node 0 into buffer 0
    {
        const int bi = node0;
        const int c0 = g_cnt[bi];
        const float4* src4 = (const float4*)(g_rbfw + (size_t)bi*NAA*WIN);
        for (int idx = f; idx < c0*2; idx += 128)
            CP_A16(smem_u32(&s_rbfw[0][0]) + idx*16, src4 + idx);
        if (chunk == 2)
            for (int idx = f; idx < c0*3; idx += 128)
                CP_A4(smem_u32(&s_dir[0][0]) + idx*4, g_dirc + (size_t)bi*NAA*3 + idx);
        if (f < c0)
            CP_A16(smem_u32(&s_meta[0][0]) + f*16, g_meta + (size_t)bi*NAA + f);
        CP_COMMIT();
    }
    CP_WAIT0();
    __syncthreads();

    const float* phiT = g_phi + t;
    const float* vT   = g_v + f;
    const ull*   wpF  = s_wp + f;

    for (int n = 0; n < NB_MSG; n++) {
        const int bi = node0 + n;
        const int cnt = g_cnt[bi];
        const int buf = n & 1;

        if (n + 1 < NB_MSG) {
            const int bj = bi + 1;
            const int c1 = g_cnt[bj];
            const int ob = buf ^ 1;
            const float4* src4 = (const float4*)(g_rbfw + (size_t)bj*NAA*WIN);
            for (int idx = f; idx < c1*2; idx += 128)
                CP_A16(smem_u32(&s_rbfw[ob][0]) + idx*16, src4 + idx);
            if (chunk == 2)
                for (int idx = f; idx < c1*3; idx += 128)
                    CP_A4(smem_u32(&s_dir[ob][0]) + idx*4, g_dirc + (size_t)bj*NAA*3 + idx);
            if (f < c1)
                CP_A16(smem_u32(&s_meta[ob][0]) + f*16, g_meta + (size_t)bj*NAA + f);
            CP_COMMIT();
        }

        float ac0 = 0.0f, ac1 = 0.0f, ac2 = 0.0f;

        float pA = 0.f, pB = 0.f;
        float vA0 = 0.f, vA1 = 0.f, vA2 = 0.f, vB0 = 0.f, vB1 = 0.f, vB2 = 0.f;
        if (cnt > 0) {
            int o0 = s_meta[buf][0].x;
            pA = __ldg(phiT + o0);
            if (chunk == 1) {
                vA0 = __ldg(vT + o0); vA1 = __ldg(vT + o0 + FF); vA2 = __ldg(vT + o0 + 2*FF);
            }
        }
        if (cnt > 1) {
            int o1 = s_meta[buf][1].x;
            pB = __ldg(phiT + o1);
            if (chunk == 1) {
                vB0 = __ldg(vT + o1); vB1 = __ldg(vT + o1 + FF); vB2 = __ldg(vT + o1 + 2*FF);
            }
        }

        int s = 0;
        for (; s + 2 <= cnt; s += 2) {
            int4 mA = s_meta[buf][s];
            int4 mB = s_meta[buf][s+1];

            float pC, pD, vC0=0.f, vC1=0.f, vC2=0.f, vD0=0.f, vD1=0.f, vD2=0.f;
            {
                int i2 = s + 2 < cnt ? s + 2 : cnt - 1;
                int i3 = s + 3 < cnt ? s + 3 : cnt - 1;
                int o2 = s_meta[buf][i2].x, o3 = s_meta[buf][i3].x;
                pC = __ldg(phiT + o2);
                pD = __ldg(phiT + o3);
                if (chunk == 1) {
                    vC0 = __ldg(vT + o2); vC1 = __ldg(vT + o2 + FF); vC2 = __ldg(vT + o2 + 2*FF);
                    vD0 = __ldg(vT + o3); vD1 = __ldg(vT + o3 + FF); vD2 = __ldg(vT + o3 + 2*FF);
                }
            }

            const ulonglong2* rwA = (const ulonglong2*)(&s_rbfw[buf][0] + s*WIN);
            const ulonglong2* rwB = (const ulonglong2*)(&s_rbfw[buf][0] + (s+1)*WIN);
            ulonglong2 aP = rwA[0], aQ = rwA[1];
            ulonglong2 bP = rwB[0], bQ = rwB[1];
            const ull* pwA = wpF + mA.y;
            const ull* pwB = wpF + mB.y;
            ull x0 = ffma2(aP.x, pwA[0*FF], 0ull);
            ull x1 = ffma2(aP.y, pwA[1*FF], 0ull);
            ull y0 = ffma2(bP.x, pwB[0*FF], 0ull);
            ull y1 = ffma2(bP.y, pwB[1*FF], 0ull);
            x0 = ffma2(aQ.x, pwA[2*FF], x0);
            x1 = ffma2(aQ.y, pwA[3*FF], x1);
            y0 = ffma2(bQ.x, pwB[2*FF], y0);
            y1 = ffma2(bQ.y, pwB[3*FF], y1);
            ull sa = add2(x0, x1), sb = add2(y0, y1);
            float la, ha, lb, hb;
            upk2(sa, la, ha); upk2(sb, lb, hb);
            float tvalA = fmaf(__int_as_float(mA.z), bias, la + ha);
            float tvalB = fmaf(__int_as_float(mB.z), bias, lb + hb);

            float xA = pA * tvalA;
            float xB = pB * tvalB;

            if (chunk == 0) {
                ac0 += xA + xB;
            } else if (chunk == 1) {
                ac0 = fmaf(xA, vA0, ac0); ac1 = fmaf(xA, vA1, ac1); ac2 = fmaf(xA, vA2, ac2);
                ac0 = fmaf(xB, vB0, ac0); ac1 = fmaf(xB, vB1, ac1); ac2 = fmaf(xB, vB2, ac2);
            } else {
                ac0 = fmaf(xA, s_dir[buf][s*3+0], ac0);
                ac1 = fmaf(xA, s_dir[buf][s*3+1], ac1);
                ac2 = fmaf(xA, s_dir[buf][s*3+2], ac2);
                ac0 = fmaf(xB, s_dir[buf][s*3+3], ac0);
                ac1 = fmaf(xB, s_dir[buf][s*3+4], ac1);
                ac2 = fmaf(xB, s_dir[buf][s*3+5], ac2);
            }

            pA = pC; pB = pD;
            vA0 = vC0; vA1 = vC1; vA2 = vC2;
            vB0 = vD0; vB1 = vD1; vB2 = vD2;
        }
        if (s < cnt) {          // odd tail
            int4 mA = s_meta[buf][s];
            const ulonglong2* rw = (const ulonglong2*)(&s_rbfw[buf][0] + s*WIN);
            ulonglong2 aP = rw[0], aQ = rw[1];
            const ull* pw = wpF + mA.y;
            ull x0 = ffma2(aP.x, pw[0*FF], 0ull);
            ull x1 = ffma2(aP.y, pw[1*FF], 0ull);
            x0 = ffma2(aQ.x, pw[2*FF], x0);
            x1 = ffma2(aQ.y, pw[3*FF], x1);
            ull sa = add2(x0, x1);
            float lo, hi; upk2(sa, lo, hi);
            float tval = fmaf(__int_as_float(mA.z), bias, lo + hi);
            float xA = pA * tval;
            if (chunk == 0) {
                ac0 += xA;
            } else if (chunk == 1) {
                ac0 = fmaf(xA, vA0, ac0); ac1 = fmaf(xA, vA1, ac1); ac2 = fmaf(xA, vA2, ac2);
            } else {
                ac0 = fmaf(xA, s_dir[buf][s*3+0], ac0);
                ac1 = fmaf(xA, s_dir[buf][s*3+1], ac1);
                ac2 = fmaf(xA, s_dir[buf][s*3+2], ac2);
            }
        }

        if (chunk == 0) {
            g_s2[(size_t)bi*FF + f] = __ldg(&g_s[(size_t)bi*FF + f]) + ac0;
        } else if (chunk == 1) {
            size_t base = (size_t)bi*F3;
            g_v2[base + f]        = __ldg(&g_v[base + f])        + ac0;
            g_v2[base + FF + f]   = __ldg(&g_v[base + FF + f])   + ac1;
            g_v2[base + 2*FF + f] = __ldg(&g_v[base + 2*FF + f]) + ac2;
        } else {
            size_t base = (size_t)bi*F3;
            g_v2b[base + f]        = ac0;
            g_v2b[base + FF + f]   = ac1;
            g_v2b[base + 2*FF + f] = ac2;
        }

        CP_WAIT0();
        __syncthreads();
    }
}

// ---------------- update block (batched x8, f32x2 node-pairs) ----------------
__global__ __launch_bounds__(384, 2)
void upd_kernel_b(const float* __restrict__ U,  const float* __restrict__ V,
                  const float* __restrict__ w1, const float* __restrict__ b1,
                  const float* __restrict__ w2, const float* __restrict__ b2) {
    extern __shared__ float usm[];
    float* sv   = usm + US_SV;
    float* s_in = usm + US_SIN;
    float* Uvs  = usm + US_UV;
    float* Vvs  = usm + US_VV;
    float* Vn   = usm + US_VN;
    float* hp   = usm + US_HP;
    float* hsh  = usm + US_HSH;
    float* ash  = usm + US_ASH;
    float* sv_t = usm + US_SVT;
    float* cat_t= usm + US_CAT;

    const int t = threadIdx.x;             // 384
    const int node0 = blockIdx.x * NB_UPD;
    const int g = t & 127;
    const int m = t >> 7;                  // 0..2

    for (int idx = t; idx < NB_UPD*F3; idx += 384) {
        float val = g_v2[(size_t)node0*F3 + idx] + g_v2b[(size_t)node0*F3 + idx];
        sv[idx] = val;
        int n = idx / F3, r = idx - n*F3;
        sv_t[r*NB_UPD + n] = val;
    }
    for (int idx = t; idx < NB_UPD*FF; idx += 384)
        s_in[idx] = g_s2[(size_t)node0*FF + idx];
    __syncthreads();

    // Phase A: Uv, Vv  (packed node-pairs)
    {
        ull aU2[NB_UPD/2] = {0,0,0,0}, aV2[NB_UPD/2] = {0,0,0,0};
        for (int k = 0; k < FF; k++) {
            float u  = __ldg(&U[k*FF + g]);
            float vw = __ldg(&V[k*FF + g]);
            ull u2  = pk2(u, u);
            ull vw2 = pk2(vw, vw);
            const ulonglong2* sp = (const ulonglong2*)(sv_t + (m*FF + k)*NB_UPD);
            ulonglong2 q0 = sp[0], q1 = sp[1];
            aU2[0] = ffma2(q0.x, u2,  aU2[0]);
            aU2[1] = ffma2(q0.y, u2,  aU2[1]);
            aU2[2] = ffma2(q1.x, u2,  aU2[2]);
            aU2[3] = ffma2(q1.y, u2,  aU2[3]);
            aV2[0] = ffma2(q0.x, vw2, aV2[0]);
            aV2[1] = ffma2(q0.y, vw2, aV2[1]);
            aV2[2] = ffma2(q1.x, vw2, aV2[2]);
            aV2[3] = ffma2(q1.y, vw2, aV2[3]);
        }
        #pragma unroll
        for (int i = 0; i < NB_UPD/2; i++) {
            float lo, hi;
            upk2(aU2[i], lo, hi);
            Uvs[((2*i)*3 + m)*FF + g]   = lo;
            Uvs[((2*i+1)*3 + m)*FF + g] = hi;
            upk2(aV2[i], lo, hi);
            Vvs[((2*i)*3 + m)*FF + g]   = lo;
            Vvs[((2*i+1)*3 + m)*FF + g] = hi;
        }
    }
    __syncthreads();

    for (int idx = t; idx < NB_UPD*FF; idx += 384) {
        int n = idx >> 7, gg = idx & 127;
        float v0 = Vvs[(n*3+0)*FF+gg], v1 = Vvs[(n*3+1)*FF+gg], v2 = Vvs[(n*3+2)*FF+gg];
        Vn[n*FF + gg] = sqrtf(v0*v0 + v1*v1 + v2*v2 + 1e-8f);
    }
    __syncthreads();

    for (int idx = t; idx < NB_UPD*2*FF; idx += 384) {
        int n = idx >> 8, k = idx & 255;
        float c = (k < FF) ? s_in[n*FF + k] : Vn[n*FF + (k-FF)];
        cat_t[k*NB_UPD + n] = c;
    }
    __syncthreads();

    // Phase B: h partial (k-split across m-groups), packed node-pairs
    {
        int k0 = m*86, k1 = (m == 2) ? 256 : (k0 + 86);
        ull acc2[NB_UPD/2] = {0,0,0,0};
        for (int k = k0; k < k1; k++) {
            float w = __ldg(&w1[k*FF + g]);
            ull w2p = pk2(w, w);
            const ulonglong2* sp = (const ulonglong2*)(cat_t + k*NB_UPD);
            ulonglong2 q0 = sp[0], q1 = sp[1];
            acc2[0] = ffma2(q0.x, w2p, acc2[0]);
            acc2[1] = ffma2(q0.y, w2p, acc2[1]);
            acc2[2] = ffma2(q1.x, w2p, acc2[2]);
            acc2[3] = ffma2(q1.y, w2p, acc2[3]);
        }
        #pragma unroll
        for (int i = 0; i < NB_UPD/2; i++) {
            float lo, hi; upk2(acc2[i], lo, hi);
            hp[(m*NB_UPD + 2*i)*FF + g]   = lo;
            hp[(m*NB_UPD + 2*i+1)*FF + g] = hi;
        }
    }
    __syncthreads();

    for (int idx = t; idx < NB_UPD*FF; idx += 384) {
        int n = idx >> 7, gg = idx & 127;
        float hs = hp[(0*NB_UPD+n)*FF+gg] + hp[(1*NB_UPD+n)*FF+gg] + hp[(2*NB_UPD+n)*FF+gg]
                 + __ldg(&b1[gg]);
        hsh[gg*NB_UPD + n] = silu_f(hs);
    }
    __syncthreads();

    // Phase C: a = h @ w2 + b2, packed node-pairs
    {
        ull acc2[NB_UPD/2];
        float bb = __ldg(&b2[t]);
        ull bb2 = pk2(bb, bb);
        #pragma unroll
        for (int i = 0; i < NB_UPD/2; i++) acc2[i] = bb2;
        for (int k = 0; k < FF; k++) {
            float w = __ldg(&w2[k*F3 + t]);
            ull w2p = pk2(w, w);
            const ulonglong2* sp = (const ulonglong2*)(hsh + k*NB_UPD);
            ulonglong2 q0 = sp[0], q1 = sp[1];
            acc2[0] = ffma2(q0.x, w2p, acc2[0]);
            acc2[1] = ffma2(q0.y, w2p, acc2[1]);
            acc2[2] = ffma2(q1.x, w2p, acc2[2]);
            acc2[3] = ffma2(q1.y, w2p, acc2[3]);
        }
        #pragma unroll
        for (int i = 0; i < NB_UPD/2; i++) {
            float lo, hi; upk2(acc2[i], lo, hi);
            ash[(2*i)*F3 + t]   = lo;
            ash[(2*i+1)*F3 + t] = hi;
        }
    }
    __syncthreads();

    for (int idx = t; idx < NB_UPD*FF; idx += 384) {
        int n = idx >> 7, gg = idx & 127;
        float avv = ash[n*F3 + gg], asv = ash[n*F3 + FF+gg], ass = ash[n*F3 + 2*FF+gg];
        float u0 = Uvs[(n*3+0)*FF+gg], u1 = Uvs[(n*3+1)*FF+gg], u2 = Uvs[(n*3+2)*FF+gg];
        float w0 = Vvs[(n*3+0)*FF+gg], w1v = Vvs[(n*3+1)*FF+gg], w2v = Vvs[(n*3+2)*FF+gg];
        float dot = u0*w0 + u1*w1v + u2*w2v;
        size_t vb = (size_t)(node0+n)*F3;
        g_v[vb + gg]        = sv[(n*3+0)*FF+gg] + avv*u0;
        g_v[vb + FF + gg]   = sv[(n*3+1)*FF+gg] + avv*u1;
        g_v[vb + 2*FF + gg] = sv[(n*3+2)*FF+gg] + avv*u2;
        g_s[(size_t)(node0+n)*FF + gg] = s_in[n*FF + gg] + asv*dot + ass;
    }
}

// ---------------- output head ----------------
__global__ void out_atom_kernel(const float* __restrict__ w1, const float* __restrict__ b1,
                                const float* __restrict__ w2, const float* __restrict__ b2) {
    const int bi = blockIdx.x;
    const int t  = threadIdx.x;                // 128
    __shared__ float ss[FF];
    __shared__ float red[FF];
    ss[t] = g_s[(size_t)bi*FF + t];
    __syncthreads();
    float acc = __ldg(&b1[t]);
    #pragma unroll 8
    for (int k = 0; k < FF; k++) acc = fmaf(ss[k], __ldg(&w1[k*FF + t]), acc);
    float h = silu_f(acc);
    red[t] = h * __ldg(&w2[t]);
    __syncthreads();
    for (int ofs = 64; ofs > 0; ofs >>= 1) {
        if (t < ofs) red[t] += red[t + ofs];
        __syncthreads();
    }
    if (t == 0) g_atom[bi] = red[0] + __ldg(&b2[0]);
}

__global__ void out_reduce_kernel(float* __restrict__ out) {
    const int b = blockIdx.x;
    const int t = threadIdx.x;                 // 64
    __shared__ float r[64];
    r[t] = (t < NAA) ? g_atom[(size_t)b*NAA + t] : 0.0f;
    __syncthreads();
    for (int ofs = 32; ofs > 0; ofs >>= 1) {
        if (t < ofs) r[t] += r[t + ofs];
        __syncthreads();
    }
    if (t == 0) out[b] = r[0];
}

// ---------------- launch ----------------
extern "C" void kernel_launch(void* const* d_in, const int* in_sizes, int n_in,
                              void* d_out, int out_size) {
    const float* pos       = (const float*)d_in[1];
    const int*   node_atom = (const int*)  d_in[3];
    const float* emb       = (const float*)d_in[4];
    const float* msg_w1    = (const float*)d_in[5];
    const float* msg_b1    = (const float*)d_in[6];
    const float* msg_w2    = (const float*)d_in[7];
    const float* msg_b2    = (const float*)d_in[8];
    const float* rbf_w     = (const float*)d_in[9];
    const float* rbf_b     = (const float*)d_in[10];
    const float* upd_U     = (const float*)d_in[11];
    const float* upd_V     = (const float*)d_in[12];
    const float* upd_w1    = (const float*)d_in[13];
    const float* upd_b1    = (const float*)d_in[14];
    const float* upd_w2    = (const float*)d_in[15];
    const float* upd_b2    = (const float*)d_in[16];
    const float* out_w1    = (const float*)d_in[17];
    const float* out_b1    = (const float*)d_in[18];
    const float* out_w2    = (const float*)d_in[19];
    const float* out_b2    = (const float*)d_in[20];

    const int upd_smem = US_TOT * sizeof(float);   // ~94 KB
    cudaFuncSetAttribute(upd_kernel_b, cudaFuncAttributeMaxDynamicSharedMemorySize, upd_smem);

    geom_kernel<<<NN, 64>>>(pos);
    init_kernel<<<NN, FF>>>(emb, node_atom);

    dim3 msg_grid(NN/NB_MSG, 3);
    for (int l = 0; l < LL; l++) {
        phi_kernel_b<<<NN/NB_PHI, 384>>>(msg_w1 + (size_t)l*FF*FF, msg_b1 + (size_t)l*FF,
                                         msg_w2 + (size_t)l*FF*F3, msg_b2 + (size_t)l*F3);
        msg_kernel_w<<<msg_grid, 128>>>(rbf_w + (size_t)l*KK*F3, rbf_b + (size_t)l*F3);
        upd_kernel_b<<<NN/NB_UPD, 384, upd_smem>>>(upd_U + (size_t)l*FF*FF, upd_V + (size_t)l*FF*FF,
                                                   upd_w1 + (size_t)l*2*FF*FF, upd_b1 + (size_t)l*FF,
                                                   upd_w2 + (size_t)l*FF*F3,   upd_b2 + (size_t)l*F3);
    }

    out_atom_kernel<<<NN, FF>>>(out_w1, out_b1, out_w2, out_b2);
    out_reduce_kernel<<<BB, 64>>>((float*)d_out);
}

// round 15
// speedup vs baseline: 1.0782x; 1.0489x over previous
#include <cuda_runtime.h>
#include <math.h>

#define BB   96
#define NAA  48
#define FF   128
#define KK   64
#define LL   6
#define NN   (BB*NAA)          // 4608 nodes
#define F3   (3*FF)            // 384
#define CUTR 5.0f
#define WIN  8                 // RBF window (2-aligned start, covers >= ±3 centers)

#define NB_PHI 16
#define NB_MSG 8
#define NB_UPD 8
#define NB_OUT 16

// upd dynamic smem layout (floats)
#define US_SV   0
#define US_SIN  (US_SV  + NB_UPD*3*FF)
#define US_UV   (US_SIN + NB_UPD*FF)
#define US_VV   (US_UV  + NB_UPD*3*FF)
#define US_VN   (US_VV  + NB_UPD*3*FF)
#define US_HP   (US_VN  + NB_UPD*FF)
#define US_HSH  (US_HP  + 3*NB_UPD*FF)
#define US_ASH  (US_HSH + FF*NB_UPD)
#define US_SVT  (US_ASH + NB_UPD*F3)
#define US_CAT  (US_SVT + F3*NB_UPD)
#define US_TOT  (US_CAT + 2*FF*NB_UPD)     // 23552 floats = 94208 B

// ---------------- device scratch ----------------
__device__ float g_s   [NN*FF];
__device__ float g_v   [NN*F3];
__device__ float g_s2  [NN*FF];
__device__ float g_v2  [NN*F3];
__device__ float g_v2b [NN*F3];
__device__ float g_phi [NN*F3];
__device__ __align__(16) float g_rbfw[NN*NAA*WIN];  // env-premult rbf window
__device__ __align__(16) int4  g_meta[NN*NAA];      // {nbr*F3, (kw>>1)*FF, env_bits, 0}
__device__ float g_dirc[NN*NAA*3];
__device__ int   g_cnt [NN];
__device__ float g_atom[NN];

// ---------------- helpers ----------------
typedef unsigned long long ull;
__device__ __forceinline__ float silu_f(float x) { return x / (1.0f + expf(-x)); }
__device__ __forceinline__ ull pk2(float lo, float hi) {
    ull r; asm("mov.b64 %0, {%1, %2};" : "=l"(r) : "f"(lo), "f"(hi)); return r;
}
__device__ __forceinline__ ull ffma2(ull a, ull b, ull c) {
    ull d; asm("fma.rn.f32x2 %0, %1, %2, %3;" : "=l"(d) : "l"(a), "l"(b), "l"(c)); return d;
}
__device__ __forceinline__ ull add2(ull a, ull b) {
    ull d; asm("add.rn.f32x2 %0, %1, %2;" : "=l"(d) : "l"(a), "l"(b)); return d;
}
__device__ __forceinline__ void upk2(ull a, float& lo, float& hi) {
    asm("mov.b64 {%0, %1}, %2;" : "=f"(lo), "=f"(hi) : "l"(a));
}
__device__ __forceinline__ unsigned smem_u32(const void* p) {
    return (unsigned)__cvta_generic_to_shared(p);
}
#define CP_A16(dst, src) asm volatile("cp.async.cg.shared.global [%0], [%1], 16;" :: "r"(dst), "l"(src))
#define CP_COMMIT()      asm volatile("cp.async.commit_group;")
#define CP_WAIT0()       asm volatile("cp.async.wait_group 0;")

// ---------------- geometry precompute + neighbor compaction ----------------
__global__ void geom_kernel(const float* __restrict__ pos) {
    const int bi = blockIdx.x;
    const int b  = bi / NAA;
    const int i  = bi % NAA;
    const int t  = threadIdx.x;                // 64

    __shared__ float sd[NAA];
    __shared__ float sdir[NAA][3];
    __shared__ int   smask[NAA];
    __shared__ int   slots[NAA];
    __shared__ int   s_cnt;

    const float* pi = pos + (size_t)(b*NAA + i)*3;
    const float pix = pi[0], piy = pi[1], piz = pi[2];

    if (t < NAA) {
        const float* pj = pos + (size_t)(b*NAA + t)*3;
        float dx = pix - pj[0], dy = piy - pj[1], dz = piz - pj[2];
        float d2 = dx*dx + dy*dy + dz*dz;
        float d  = (t == i) ? 1.0f : sqrtf(d2);
        smask[t] = (t != i) && (d < CUTR);
        sd[t] = d;
        float inv = 1.0f / d;
        sdir[t][0] = dx*inv; sdir[t][1] = dy*inv; sdir[t][2] = dz*inv;
    }
    __syncthreads();
    if (t == 0) {
        int c = 0;
        for (int j = 0; j < NAA; j++) if (smask[j]) slots[c++] = j;
        s_cnt = c;
        g_cnt[bi] = c;
    }
    __syncthreads();
    const int cnt = s_cnt;

    const float GAMMA = (float)(1.0 / ((5.0/64.0)*(5.0/64.0) + 1e-9));
    const float STEP  = (float)(5.0 / 63.0);
    const float PI_F  = 3.14159265358979323846f;

    for (int s = 0; s < cnt; s++) {
        int j = slots[s];
        float d = sd[j];
        float env = 0.5f * (cosf(PI_F * d / CUTR) + 1.0f);
        int ic = __float2int_rn(d / STEP);
        int kw = (ic - 3) & ~1;                // 2-aligned start, coverage >= ±3 centers
        if (kw < 0) kw = 0;
        if (kw > KK - WIN) kw = KK - WIN;      // 56, even
        if (t < WIN) {
            float center = STEP * (float)(kw + t);
            float diff = d - center;
            g_rbfw[((size_t)bi*NAA + s)*WIN + t] = env * expf(-GAMMA * diff * diff);
        } else if (t == WIN) {
            g_meta[(size_t)bi*NAA + s] =
                make_int4((b*NAA + j)*F3, (kw >> 1)*FF, __float_as_int(env), 0);
            g_dirc[((size_t)bi*NAA + s)*3 + 0] = sdir[j][0];
            g_dirc[((size_t)bi*NAA + s)*3 + 1] = sdir[j][1];
            g_dirc[((size_t)bi*NAA + s)*3 + 2] = sdir[j][2];
        }
    }
}

// ---------------- init ----------------
__global__ void init_kernel(const float* __restrict__ emb,
                            const int*   __restrict__ node_atom) {
    const int bi = blockIdx.x;
    const int t  = threadIdx.x;                // 128
    const int a  = node_atom[bi];
    g_s[(size_t)bi*FF + t] = emb[(size_t)a*FF + t];
    g_v[(size_t)bi*F3 + t]          = 0.0f;
    g_v[(size_t)bi*F3 + FF + t]     = 0.0f;
    g_v[(size_t)bi*F3 + 2*FF + t]   = 0.0f;
}

// ---------------- phi (batched, split-k first GEMM across 3 warp-groups) ---------
__global__ __launch_bounds__(384)
void phi_kernel_b(const float* __restrict__ w1, const float* __restrict__ b1,
                  const float* __restrict__ w2, const float* __restrict__ b2) {
    __shared__ __align__(16) float ss[FF][NB_PHI];
    __shared__ __align__(16) float sh[FF][NB_PHI];
    __shared__ __align__(16) float hp[3][FF][NB_PHI];   // split-k partials
    const int t = threadIdx.x;             // 384
    const int g = t & 127;
    const int m = t >> 7;                  // 0..2
    const int node0 = blockIdx.x * NB_PHI;

    for (int idx = t; idx < NB_PHI*FF; idx += 384) {
        int n = idx >> 7, k = idx & 127;
        ss[k][n] = g_s[(size_t)(node0+n)*FF + k];
    }
    __syncthreads();

    // first GEMM: split k across m-groups
    {
        const int k0 = (m == 0) ? 0 : (m == 1 ? 43 : 86);
        const int k1 = (m == 0) ? 43 : (m == 1 ? 86 : 128);
        ull acc2[NB_PHI/2] = {0,0,0,0,0,0,0,0};
        for (int k = k0; k < k1; k++) {
            float w = __ldg(&w1[k*FF + g]);
            ull w2p = pk2(w, w);
            const ulonglong2* sp = (const ulonglong2*)&ss[k][0];
            ulonglong2 q0 = sp[0], q1 = sp[1], q2 = sp[2], q3 = sp[3];
            acc2[0] = ffma2(q0.x, w2p, acc2[0]);
            acc2[1] = ffma2(q0.y, w2p, acc2[1]);
            acc2[2] = ffma2(q1.x, w2p, acc2[2]);
            acc2[3] = ffma2(q1.y, w2p, acc2[3]);
            acc2[4] = ffma2(q2.x, w2p, acc2[4]);
            acc2[5] = ffma2(q2.y, w2p, acc2[5]);
            acc2[6] = ffma2(q3.x, w2p, acc2[6]);
            acc2[7] = ffma2(q3.y, w2p, acc2[7]);
        }
        #pragma unroll
        for (int i = 0; i < NB_PHI/2; i++) {
            float lo, hi; upk2(acc2[i], lo, hi);
            hp[m][g][2*i]   = lo;
            hp[m][g][2*i+1] = hi;
        }
    }
    __syncthreads();

    for (int idx = t; idx < FF*NB_PHI; idx += 384) {
        int k = idx >> 4, n = idx & 15;
        float hs = hp[0][k][n] + hp[1][k][n] + hp[2][k][n] + __ldg(&b1[k]);
        sh[k][n] = silu_f(hs);
    }
    __syncthreads();

    // second GEMM: all 384 threads, one output column each
    {
        ull acc2[NB_PHI/2];
        float bb = __ldg(&b2[t]);
        ull bb2 = pk2(bb, bb);
        #pragma unroll
        for (int i = 0; i < NB_PHI/2; i++) acc2[i] = bb2;
        for (int k = 0; k < FF; k++) {
            float w = __ldg(&w2[k*F3 + t]);
            ull w2p = pk2(w, w);
            const ulonglong2* sp = (const ulonglong2*)&sh[k][0];
            ulonglong2 q0 = sp[0], q1 = sp[1], q2 = sp[2], q3 = sp[3];
            acc2[0] = ffma2(q0.x, w2p, acc2[0]);
            acc2[1] = ffma2(q0.y, w2p, acc2[1]);
            acc2[2] = ffma2(q1.x, w2p, acc2[2]);
            acc2[3] = ffma2(q1.y, w2p, acc2[3]);
            acc2[4] = ffma2(q2.x, w2p, acc2[4]);
            acc2[5] = ffma2(q2.y, w2p, acc2[5]);
            acc2[6] = ffma2(q3.x, w2p, acc2[6]);
            acc2[7] = ffma2(q3.y, w2p, acc2[7]);
        }
        #pragma unroll
        for (int i = 0; i < NB_PHI/2; i++) {
            float lo, hi; upk2(acc2[i], lo, hi);
            g_phi[(size_t)(node0+2*i)*F3   + t] = lo;
            g_phi[(size_t)(node0+2*i+1)*F3 + t] = hi;
        }
    }
}

// ---------------- message block: WIN=8 + int4 meta + cp.async + prefetch ----------
// dir for chunk 2 comes via broadcast LDG prefetch (same registers as chunk 1's v)
__global__ __launch_bounds__(128, 6)
void msg_kernel_w(const float* __restrict__ rbf_w, const float* __restrict__ rbf_b) {
    __shared__ __align__(16) ull   s_wp[(KK/2)*FF];     // 32 KB packed W pairs [p][f]
    __shared__ __align__(16) float s_rbfw[2][NAA*WIN];  // 3 KB double-buffered
    __shared__ __align__(16) int4  s_meta[2][NAA];      // 1.5 KB

    const int f = threadIdx.x;                 // 128
    const int chunk = blockIdx.y;              // 0..2
    const int t = chunk*FF + f;
    const int node0 = blockIdx.x * NB_MSG;

    for (int idx = f; idx < (KK/2)*FF; idx += 128) {
        int p = idx >> 7, ff = idx & 127;
        s_wp[idx] = pk2(__ldg(&rbf_w[(2*p)*F3   + chunk*FF + ff]),
                        __ldg(&rbf_w[(2*p+1)*F3 + chunk*FF + ff]));
    }
    const float bias = __ldg(&rbf_b[t]);

    // async-stage node 0 into buffer 0
    {
        const int bi = node0;
        const int c0 = g_cnt[bi];
        const float4* src4 = (const float4*)(g_rbfw + (size_t)bi*NAA*WIN);
        for (int idx = f; idx < c0*2; idx += 128)
            CP_A16(smem_u32(&s_rbfw[0][0]) + idx*16, src4 + idx);
        if (f < c0)
            CP_A16(smem_u32(&s_meta[0][0]) + f*16, g_meta + (size_t)bi*NAA + f);
        CP_COMMIT();
    }
    CP_WAIT0();
    __syncthreads();

    const float* phiT = g_phi + t;
    const float* vT   = g_v + f;

    for (int n = 0; n < NB_MSG; n++) {
        const int bi = node0 + n;
        const int cnt = g_cnt[bi];
        const int buf = n & 1;
        const float* dirB = g_dirc + (size_t)bi*NAA*3;

        if (n + 1 < NB_MSG) {
            const int bj = bi + 1;
            const int c1 = g_cnt[bj];
            const int ob = buf ^ 1;
            const float4* src4 = (const float4*)(g_rbfw + (size_t)bj*NAA*WIN);
            for (int idx = f; idx < c1*2; idx += 128)
                CP_A16(smem_u32(&s_rbfw[ob][0]) + idx*16, src4 + idx);
            if (f < c1)
                CP_A16(smem_u32(&s_meta[ob][0]) + f*16, g_meta + (size_t)bj*NAA + f);
            CP_COMMIT();
        }

        float ac0 = 0.0f, ac1 = 0.0f, ac2 = 0.0f;

        float pA = 0.f, pB = 0.f;
        float vA0 = 0.f, vA1 = 0.f, vA2 = 0.f, vB0 = 0.f, vB1 = 0.f, vB2 = 0.f;
        if (cnt > 0) {
            int o0 = s_meta[buf][0].x;
            pA = __ldg(phiT + o0);
            if (chunk == 1) {
                vA0 = __ldg(vT + o0); vA1 = __ldg(vT + o0 + FF); vA2 = __ldg(vT + o0 + 2*FF);
            } else if (chunk == 2) {
                vA0 = __ldg(dirB + 0); vA1 = __ldg(dirB + 1); vA2 = __ldg(dirB + 2);
            }
        }
        if (cnt > 1) {
            int o1 = s_meta[buf][1].x;
            pB = __ldg(phiT + o1);
            if (chunk == 1) {
                vB0 = __ldg(vT + o1); vB1 = __ldg(vT + o1 + FF); vB2 = __ldg(vT + o1 + 2*FF);
            } else if (chunk == 2) {
                vB0 = __ldg(dirB + 3); vB1 = __ldg(dirB + 4); vB2 = __ldg(dirB + 5);
            }
        }

        int s = 0;
        for (; s + 2 <= cnt; s += 2) {
            int4 mA = s_meta[buf][s];
            int4 mB = s_meta[buf][s+1];

            float pC, pD, vC0=0.f, vC1=0.f, vC2=0.f, vD0=0.f, vD1=0.f, vD2=0.f;
            {
                int i2 = s + 2 < cnt ? s + 2 : cnt - 1;
                int i3 = s + 3 < cnt ? s + 3 : cnt - 1;
                int o2 = s_meta[buf][i2].x, o3 = s_meta[buf][i3].x;
                pC = __ldg(phiT + o2);
                pD = __ldg(phiT + o3);
                if (chunk == 1) {
                    vC0 = __ldg(vT + o2); vC1 = __ldg(vT + o2 + FF); vC2 = __ldg(vT + o2 + 2*FF);
                    vD0 = __ldg(vT + o3); vD1 = __ldg(vT + o3 + FF); vD2 = __ldg(vT + o3 + 2*FF);
                } else if (chunk == 2) {
                    const float* dp2 = dirB + i2*3;
                    const float* dp3 = dirB + i3*3;
                    vC0 = __ldg(dp2); vC1 = __ldg(dp2 + 1); vC2 = __ldg(dp2 + 2);
                    vD0 = __ldg(dp3); vD1 = __ldg(dp3 + 1); vD2 = __ldg(dp3 + 2);
                }
            }

            const ulonglong2* rwA = (const ulonglong2*)(&s_rbfw[buf][0] + s*WIN);
            const ulonglong2* rwB = (const ulonglong2*)(&s_rbfw[buf][0] + (s+1)*WIN);
            ulonglong2 aP = rwA[0], aQ = rwA[1];
            ulonglong2 bP = rwB[0], bQ = rwB[1];
            const ull* pwA = s_wp + f + mA.y;
            const ull* pwB = s_wp + f + mB.y;
            ull x0 = ffma2(aP.x, pwA[0*FF], 0ull);
            ull x1 = ffma2(aP.y, pwA[1*FF], 0ull);
            ull y0 = ffma2(bP.x, pwB[0*FF], 0ull);
            ull y1 = ffma2(bP.y, pwB[1*FF], 0ull);
            x0 = ffma2(aQ.x, pwA[2*FF], x0);
            x1 = ffma2(aQ.y, pwA[3*FF], x1);
            y0 = ffma2(bQ.x, pwB[2*FF], y0);
            y1 = ffma2(bQ.y, pwB[3*FF], y1);
            ull sa = add2(x0, x1), sb = add2(y0, y1);
            float la, ha, lb, hb;
            upk2(sa, la, ha); upk2(sb, lb, hb);
            float tvalA = fmaf(__int_as_float(mA.z), bias, la + ha);
            float tvalB = fmaf(__int_as_float(mB.z), bias, lb + hb);

            float xA = pA * tvalA;
            float xB = pB * tvalB;

            if (chunk == 0) {
                ac0 += xA + xB;
            } else {
                ac0 = fmaf(xA, vA0, ac0); ac1 = fmaf(xA, vA1, ac1); ac2 = fmaf(xA, vA2, ac2);
                ac0 = fmaf(xB, vB0, ac0); ac1 = fmaf(xB, vB1, ac1); ac2 = fmaf(xB, vB2, ac2);
            }

            pA = pC; pB = pD;
            vA0 = vC0; vA1 = vC1; vA2 = vC2;
            vB0 = vD0; vB1 = vD1; vB2 = vD2;
        }
        if (s < cnt) {          // odd tail (uses pA / vA)
            int4 mA = s_meta[buf][s];
            const ulonglong2* rw = (const ulonglong2*)(&s_rbfw[buf][0] + s*WIN);
            ulonglong2 aP = rw[0], aQ = rw[1];
            const ull* pw = s_wp + f + mA.y;
            ull x0 = ffma2(aP.x, pw[0*FF], 0ull);
            ull x1 = ffma2(aP.y, pw[1*FF], 0ull);
            x0 = ffma2(aQ.x, pw[2*FF], x0);
            x1 = ffma2(aQ.y, pw[3*FF], x1);
            ull sa = add2(x0, x1);
            float lo, hi; upk2(sa, lo, hi);
            float tval = fmaf(__int_as_float(mA.z), bias, lo + hi);
            float xA = pA * tval;
            if (chunk == 0) {
                ac0 += xA;
            } else {
                ac0 = fmaf(xA, vA0, ac0); ac1 = fmaf(xA, vA1, ac1); ac2 = fmaf(xA, vA2, ac2);
            }
        }

        if (chunk == 0) {
            g_s2[(size_t)bi*FF + f] = __ldg(&g_s[(size_t)bi*FF + f]) + ac0;
        } else if (chunk == 1) {
            size_t base = (size_t)bi*F3;
            g_v2[base + f]        = __ldg(&g_v[base + f])        + ac0;
            g_v2[base + FF + f]   = __ldg(&g_v[base + FF + f])   + ac1;
            g_v2[base + 2*FF + f] = __ldg(&g_v[base + 2*FF + f]) + ac2;
        } else {
            size_t base = (size_t)bi*F3;
            g_v2b[base + f]        = ac0;
            g_v2b[base + FF + f]   = ac1;
            g_v2b[base + 2*FF + f] = ac2;
        }

        CP_WAIT0();
        __syncthreads();
    }
}

// ---------------- update block (batched x8, f32x2 node-pairs) ----------------
__global__ __launch_bounds__(384, 2)
void upd_kernel_b(const float* __restrict__ U,  const float* __restrict__ V,
                  const float* __restrict__ w1, const float* __restrict__ b1,
                  const float* __restrict__ w2, const float* __restrict__ b2) {
    extern __shared__ float usm[];
    float* sv   = usm + US_SV;
    float* s_in = usm + US_SIN;
    float* Uvs  = usm + US_UV;
    float* Vvs  = usm + US_VV;
    float* Vn   = usm + US_VN;
    float* hp   = usm + US_HP;
    float* hsh  = usm + US_HSH;
    float* ash  = usm + US_ASH;
    float* sv_t = usm + US_SVT;
    float* cat_t= usm + US_CAT;

    const int t = threadIdx.x;             // 384
    const int node0 = blockIdx.x * NB_UPD;
    const int g = t & 127;
    const int m = t >> 7;                  // 0..2

    for (int idx = t; idx < NB_UPD*F3; idx += 384) {
        float val = g_v2[(size_t)node0*F3 + idx] + g_v2b[(size_t)node0*F3 + idx];
        sv[idx] = val;
        int n = idx / F3, r = idx - n*F3;
        sv_t[r*NB_UPD + n] = val;
    }
    for (int idx = t; idx < NB_UPD*FF; idx += 384)
        s_in[idx] = g_s2[(size_t)node0*FF + idx];
    __syncthreads();

    // Phase A: Uv, Vv  (packed node-pairs)
    {
        ull aU2[NB_UPD/2] = {0,0,0,0}, aV2[NB_UPD/2] = {0,0,0,0};
        for (int k = 0; k < FF; k++) {
            float u  = __ldg(&U[k*FF + g]);
            float vw = __ldg(&V[k*FF + g]);
            ull u2  = pk2(u, u);
            ull vw2 = pk2(vw, vw);
            const ulonglong2* sp = (const ulonglong2*)(sv_t + (m*FF + k)*NB_UPD);
            ulonglong2 q0 = sp[0], q1 = sp[1];
            aU2[0] = ffma2(q0.x, u2,  aU2[0]);
            aU2[1] = ffma2(q0.y, u2,  aU2[1]);
            aU2[2] = ffma2(q1.x, u2,  aU2[2]);
            aU2[3] = ffma2(q1.y, u2,  aU2[3]);
            aV2[0] = ffma2(q0.x, vw2, aV2[0]);
            aV2[1] = ffma2(q0.y, vw2, aV2[1]);
            aV2[2] = ffma2(q1.x, vw2, aV2[2]);
            aV2[3] = ffma2(q1.y, vw2, aV2[3]);
        }
        #pragma unroll
        for (int i = 0; i < NB_UPD/2; i++) {
            float lo, hi;
            upk2(aU2[i], lo, hi);
            Uvs[((2*i)*3 + m)*FF + g]   = lo;
            Uvs[((2*i+1)*3 + m)*FF + g] = hi;
            upk2(aV2[i], lo, hi);
            Vvs[((2*i)*3 + m)*FF + g]   = lo;
            Vvs[((2*i+1)*3 + m)*FF + g] = hi;
        }
    }
    __syncthreads();

    for (int idx = t; idx < NB_UPD*FF; idx += 384) {
        int n = idx >> 7, gg = idx & 127;
        float v0 = Vvs[(n*3+0)*FF+gg], v1 = Vvs[(n*3+1)*FF+gg], v2 = Vvs[(n*3+2)*FF+gg];
        Vn[n*FF + gg] = sqrtf(v0*v0 + v1*v1 + v2*v2 + 1e-8f);
    }
    __syncthreads();

    for (int idx = t; idx < NB_UPD*2*FF; idx += 384) {
        int n = idx >> 8, k = idx & 255;
        float c = (k < FF) ? s_in[n*FF + k] : Vn[n*FF + (k-FF)];
        cat_t[k*NB_UPD + n] = c;
    }
    __syncthreads();

    // Phase B: h partial (k-split across m-groups), packed node-pairs
    {
        int k0 = m*86, k1 = (m == 2) ? 256 : (k0 + 86);
        ull acc2[NB_UPD/2] = {0,0,0,0};
        for (int k = k0; k < k1; k++) {
            float w = __ldg(&w1[k*FF + g]);
            ull w2p = pk2(w, w);
            const ulonglong2* sp = (const ulonglong2*)(cat_t + k*NB_UPD);
            ulonglong2 q0 = sp[0], q1 = sp[1];
            acc2[0] = ffma2(q0.x, w2p, acc2[0]);
            acc2[1] = ffma2(q0.y, w2p, acc2[1]);
            acc2[2] = ffma2(q1.x, w2p, acc2[2]);
            acc2[3] = ffma2(q1.y, w2p, acc2[3]);
        }
        #pragma unroll
        for (int i = 0; i < NB_UPD/2; i++) {
            float lo, hi; upk2(acc2[i], lo, hi);
            hp[(m*NB_UPD + 2*i)*FF + g]   = lo;
            hp[(m*NB_UPD + 2*i+1)*FF + g] = hi;
        }
    }
    __syncthreads();

    for (int idx = t; idx < NB_UPD*FF; idx += 384) {
        int n = idx >> 7, gg = idx & 127;
        float hs = hp[(0*NB_UPD+n)*FF+gg] + hp[(1*NB_UPD+n)*FF+gg] + hp[(2*NB_UPD+n)*FF+gg]
                 + __ldg(&b1[gg]);
        hsh[gg*NB_UPD + n] = silu_f(hs);
    }
    __syncthreads();

    // Phase C: a = h @ w2 + b2, packed node-pairs
    {
        ull acc2[NB_UPD/2];
        float bb = __ldg(&b2[t]);
        ull bb2 = pk2(bb, bb);
        #pragma unroll
        for (int i = 0; i < NB_UPD/2; i++) acc2[i] = bb2;
        for (int k = 0; k < FF; k++) {
            float w = __ldg(&w2[k*F3 + t]);
            ull w2p = pk2(w, w);
            const ulonglong2* sp = (const ulonglong2*)(hsh + k*NB_UPD);
            ulonglong2 q0 = sp[0], q1 = sp[1];
            acc2[0] = ffma2(q0.x, w2p, acc2[0]);
            acc2[1] = ffma2(q0.y, w2p, acc2[1]);
            acc2[2] = ffma2(q1.x, w2p, acc2[2]);
            acc2[3] = ffma2(q1.y, w2p, acc2[3]);
        }
        #pragma unroll
        for (int i = 0; i < NB_UPD/2; i++) {
            float lo, hi; upk2(acc2[i], lo, hi);
            ash[(2*i)*F3 + t]   = lo;
            ash[(2*i+1)*F3 + t] = hi;
        }
    }
    __syncthreads();

    for (int idx = t; idx < NB_UPD*FF; idx += 384) {
        int n = idx >> 7, gg = idx & 127;
        float avv = ash[n*F3 + gg], asv = ash[n*F3 + FF+gg], ass = ash[n*F3 + 2*FF+gg];
        float u0 = Uvs[(n*3+0)*FF+gg], u1 = Uvs[(n*3+1)*FF+gg], u2 = Uvs[(n*3+2)*FF+gg];
        float w0 = Vvs[(n*3+0)*FF+gg], w1v = Vvs[(n*3+1)*FF+gg], w2v = Vvs[(n*3+2)*FF+gg];
        float dot = u0*w0 + u1*w1v + u2*w2v;
        size_t vb = (size_t)(node0+n)*F3;
        g_v[vb + gg]        = sv[(n*3+0)*FF+gg] + avv*u0;
        g_v[vb + FF + gg]   = sv[(n*3+1)*FF+gg] + avv*u1;
        g_v[vb + 2*FF + gg] = sv[(n*3+2)*FF+gg] + avv*u2;
        g_s[(size_t)(node0+n)*FF + gg] = s_in[n*FF + gg] + asv*dot + ass;
    }
}

// ---------------- output head (batched x16) ----------------
__global__ __launch_bounds__(128)
void out_atom_kernel_b(const float* __restrict__ w1, const float* __restrict__ b1,
                       const float* __restrict__ w2, const float* __restrict__ b2) {
    __shared__ __align__(16) float ss [FF][NB_OUT];
    __shared__ __align__(16) float red[FF][NB_OUT];
    const int t = threadIdx.x;             // 128
    const int node0 = blockIdx.x * NB_OUT;

    for (int idx = t; idx < NB_OUT*FF; idx += 128) {
        int n = idx >> 7, k = idx & 127;
        ss[k][n] = g_s[(size_t)(node0+n)*FF + k];
    }
    __syncthreads();

    float acc[NB_OUT];
    float bb = __ldg(&b1[t]);
    #pragma unroll
    for (int n = 0; n < NB_OUT; n++) acc[n] = bb;
    for (int k = 0; k < FF; k++) {
        float w = __ldg(&w1[k*FF + t]);
        #pragma unroll
        for (int n = 0; n < NB_OUT; n++) acc[n] = fmaf(ss[k][n], w, acc[n]);
    }
    float w2t = __ldg(&w2[t]);
    #pragma unroll
    for (int n = 0; n < NB_OUT; n++) red[t][n] = silu_f(acc[n]) * w2t;
    __syncthreads();

    for (int ofs = 64; ofs > 0; ofs >>= 1) {
        if (t < ofs) {
            #pragma unroll
            for (int n = 0; n < NB_OUT; n++) red[t][n] += red[t + ofs][n];
        }
        __syncthreads();
    }
    if (t < NB_OUT) g_atom[node0 + t] = red[0][t] + __ldg(&b2[0]);
}

__global__ void out_reduce_kernel(float* __restrict__ out) {
    const int b = blockIdx.x;
    const int t = threadIdx.x;                 // 64
    __shared__ float r[64];
    r[t] = (t < NAA) ? g_atom[(size_t)b*NAA + t] : 0.0f;
    __syncthreads();
    for (int ofs = 32; ofs > 0; ofs >>= 1) {
        if (t < ofs) r[t] += r[t + ofs];
        __syncthreads();
    }
    if (t == 0) out[b] = r[0];
}

// ---------------- launch ----------------
extern "C" void kernel_launch(void* const* d_in, const int* in_sizes, int n_in,
                              void* d_out, int out_size) {
    const float* pos       = (const float*)d_in[1];
    const int*   node_atom = (const int*)  d_in[3];
    const float* emb       = (const float*)d_in[4];
    const float* msg_w1    = (const float*)d_in[5];
    const float* msg_b1    = (const float*)d_in[6];
    const float* msg_w2    = (const float*)d_in[7];
    const float* msg_b2    = (const float*)d_in[8];
    const float* rbf_w     = (const float*)d_in[9];
    const float* rbf_b     = (const float*)d_in[10];
    const float* upd_U     = (const float*)d_in[11];
    const float* upd_V     = (const float*)d_in[12];
    const float* upd_w1    = (const float*)d_in[13];
    const float* upd_b1    = (const float*)d_in[14];
    const float* upd_w2    = (const float*)d_in[15];
    const float* upd_b2    = (const float*)d_in[16];
    const float* out_w1    = (const float*)d_in[17];
    const float* out_b1    = (const float*)d_in[18];
    const float* out_w2    = (const float*)d_in[19];
    const float* out_b2    = (const float*)d_in[20];

    const int upd_smem = US_TOT * sizeof(float);   // ~94 KB
    cudaFuncSetAttribute(upd_kernel_b, cudaFuncAttributeMaxDynamicSharedMemorySize, upd_smem);

    geom_kernel<<<NN, 64>>>(pos);
    init_kernel<<<NN, FF>>>(emb, node_atom);

    dim3 msg_grid(NN/NB_MSG, 3);
    for (int l = 0; l < LL; l++) {
        phi_kernel_b<<<NN/NB_PHI, 384>>>(msg_w1 + (size_t)l*FF*FF, msg_b1 + (size_t)l*FF,
                                         msg_w2 + (size_t)l*FF*F3, msg_b2 + (size_t)l*F3);
        msg_kernel_w<<<msg_grid, 128>>>(rbf_w + (size_t)l*KK*F3, rbf_b + (size_t)l*F3);
        upd_kernel_b<<<NN/NB_UPD, 384, upd_smem>>>(upd_U + (size_t)l*FF*FF, upd_V + (size_t)l*FF*FF,
                                                   upd_w1 + (size_t)l*2*FF*FF, upd_b1 + (size_t)l*FF,
                                                   upd_w2 + (size_t)l*FF*F3,   upd_b2 + (size_t)l*F3);
    }

    out_atom_kernel_b<<<NN/NB_OUT, 128>>>(out_w1, out_b1, out_w2, out_b2);
    out_reduce_kernel<<<BB, 64>>>((float*)d_out);
}